// round 9
// baseline (speedup 1.0000x reference)
#include <cuda_runtime.h>
#include <cuda_bf16.h>
#include <math_constants.h>

// CRF neg-log-likelihood, GB300 sm_103a.
// ONE WARP per batch row (64 CTAs x 32 threads) -> BAR.SYNC nw=1 floor ~3 cyc,
// no cross-warp skew. Lane l<25 owns output columns (2l, 2l+1). GEMV: 7 LDS.128
// fetch the 25 partition pair-words; 50 HFMA2 use half-selected broadcasts
// (splat folds into HFMA2 .H0_H0/.H1_H1). Accumulator pair IS (q_2l,q_2l+1):
// no horizontal reduce. exp(feats) precomputed into smem as bf162 pairs.
// Rescale by p_prev[0] every 4 steps. Gold score epilogue; last CTA reduces.

namespace {
constexpr int NTAG   = 50;
constexpr int TSTART = NTAG - 2;   // 48
constexpr int TSTOP  = NTAG - 1;   // 49
constexpr int BATCH  = 64;
constexpr int SEQ    = 512;
constexpr int NTHR   = 32;
constexpr int NPW    = 25;         // partition pair-words (u32, 2 bf16 each)
constexpr int BUFW   = 28;         // buffer words (7 float4), 3 zero pads
// dynamic smem: s_ef[SEQ*NPW] u32 pairs, then s_mask[SEQ+4]
constexpr int SMEM_EF_WORDS = SEQ * NPW;
constexpr int SMEM_BYTES    = (SMEM_EF_WORDS + SEQ + 4) * 4;
}

__device__ float    g_partial[BATCH];
__device__ unsigned g_ticket = 0;

__device__ __forceinline__ float warpSumF(float v) {
#pragma unroll
    for (int o = 16; o > 0; o >>= 1) v += __shfl_xor_sync(0xffffffffu, v, o);
    return v;
}
__device__ __forceinline__ int warpSumI(int v) {
#pragma unroll
    for (int o = 16; o > 0; o >>= 1) v += __shfl_xor_sync(0xffffffffu, v, o);
    return v;
}
__device__ __forceinline__ __nv_bfloat162 u2b(unsigned u) {
    return *reinterpret_cast<__nv_bfloat162*>(&u);
}
__device__ __forceinline__ unsigned b2u(__nv_bfloat162 b) {
    return *reinterpret_cast<unsigned*>(&b);
}
// splats that ptxas folds into HFMA2 half-lane source selectors
__device__ __forceinline__ __nv_bfloat162 lo2(unsigned w) {
    return __bfloat162bfloat162(__low2bfloat16(u2b(w)));
}
__device__ __forceinline__ __nv_bfloat162 hi2(unsigned w) {
    return __bfloat162bfloat162(__high2bfloat16(u2b(w)));
}

// GEMV for this lane's column pair: acc = sum_i p_i * (et[i][2l], et[i][2l+1])
__device__ __forceinline__ __nv_bfloat162 gemv25(
    const unsigned (&w)[BUFW], const __nv_bfloat162 (&et2)[NTAG])
{
    __nv_bfloat162 z  = __floats2bfloat162_rn(0.f, 0.f);
    __nv_bfloat162 a0 = z, a1 = z, a2 = z, a3 = z;
#pragma unroll
    for (int k = 0; k < NPW; k++) {
        if (k & 1) {
            a2 = __hfma2(lo2(w[k]), et2[2 * k],     a2);
            a3 = __hfma2(hi2(w[k]), et2[2 * k + 1], a3);
        } else {
            a0 = __hfma2(lo2(w[k]), et2[2 * k],     a0);
            a1 = __hfma2(hi2(w[k]), et2[2 * k + 1], a1);
        }
    }
    return __hadd2(__hadd2(a0, a1), __hadd2(a2, a3));
}

// One recursion step. On entry: efu = ef pair(t), m = mask[t]; exits prefetched t+1.
template <bool RESCALE>
__device__ __forceinline__ void fwd_step(
    int t, int l, bool act,
    const unsigned* __restrict__ src,   // 28-word partition buffer
    unsigned*       __restrict__ dst,
    const __nv_bfloat162 (&et2)[NTAG],
    unsigned& efu, int& m, unsigned& pju, float& offset,
    const unsigned* __restrict__ s_ef,
    const int*      __restrict__ s_mask,
    int lc)
{
    // load all 25 pair-words (7 LDS.128, broadcast)
    unsigned w[BUFW];
#pragma unroll
    for (int q = 0; q < 7; q++) {
        float4 v = ((const float4*)src)[q];
        w[4 * q + 0] = __float_as_uint(v.x);
        w[4 * q + 1] = __float_as_uint(v.y);
        w[4 * q + 2] = __float_as_uint(v.z);
        w[4 * q + 3] = __float_as_uint(v.w);
    }

    float p0f = 1.f, rp0 = 1.f;
    if (RESCALE) {
        p0f = __uint_as_float(w[0] << 16);   // p[0] as fp32
        rp0 = __frcp_rn(p0f);                // MUFU, off critical path
    }

    __nv_bfloat162 acc = gemv25(w, et2);
    unsigned q2u = b2u(__hmul2(acc, u2b(efu)));   // * (ef_2l, ef_2l+1)

    q2u = m ? q2u : pju;                          // masked: carry previous

    if (RESCALE)
        q2u = b2u(__hmul2(u2b(q2u), __float2bfloat162_rn(rp0)));

    pju = q2u;
    if (act) dst[l] = q2u;                        // STS.32

    // off-path prefetches (smem only)
    efu = s_ef[(t + 1) * NPW + lc];
    m   = s_mask[t + 1];
    if (RESCALE) offset += __logf(p0f);

    __syncthreads();                              // BAR.SYNC nw=1, floor ~3
}

__global__ void __launch_bounds__(NTHR, 1)
crf_kernel(const float* __restrict__ feats,
           const int*   __restrict__ mask,
           const int*   __restrict__ tags,
           const float* __restrict__ trans,
           float*       __restrict__ out)
{
    const int b    = blockIdx.x;
    const int l    = threadIdx.x;
    const bool act = (l < NPW);
    const int lc   = act ? l : NPW - 1;

    extern __shared__ unsigned dyn[];
    unsigned* s_ef   = dyn;                          // [SEQ][NPW]
    int*      s_mask = (int*)(dyn + SMEM_EF_WORDS);  // [SEQ+4]

    __shared__ __align__(16) unsigned spA[BUFW];
    __shared__ __align__(16) unsigned spB[BUFW];
    __shared__ float s_red;

    const float* fb = feats + (long long)b * SEQ * NTAG;
    const int*   mb = mask  + b * SEQ;
    const int*   tb = tags  + b * SEQ;

    // ---- prologue ----
    for (int t = l; t < SEQ; t += NTHR) s_mask[t] = mb[t];
    if (l < 4) s_mask[SEQ + l] = 0;

    // exp(feats) pairs: s_ef[t*25+k] = (bf16 e^f[t][2k], bf16 e^f[t][2k+1])
    for (int idx = l; idx < SEQ * NPW; idx += NTHR) {
        int t = idx / NPW;
        int k = idx - t * NPW;
        float2 v = *(const float2*)(fb + t * NTAG + 2 * k);
        s_ef[idx] = b2u(__floats2bfloat162_rn(__expf(v.x), __expf(v.y)));
    }

    // exp(transitions) for this lane's column pair: et2[i] = (e^T[i][2l], e^T[i][2l+1])
    __nv_bfloat162 et2[NTAG];
#pragma unroll
    for (int i = 0; i < NTAG; i++) {
        float e0 = act ? __expf(trans[i * NTAG + 2 * lc])     : 0.f;
        float e1 = act ? __expf(trans[i * NTAG + 2 * lc + 1]) : 0.f;
        et2[i] = __floats2bfloat162_rn(e0, e1);
    }

    // t = 0: normalize by partition0[tag 0]
    const float off0   = fb[0] + trans[TSTART * NTAG + 0];
    float       offset = off0;
    float2 f0 = *(const float2*)(fb + 2 * lc);
    float pa = __expf(f0.x + trans[TSTART * NTAG + 2 * lc]     - off0);
    float pb = __expf(f0.y + trans[TSTART * NTAG + 2 * lc + 1] - off0);
    unsigned pju = b2u(__floats2bfloat162_rn(pa, pb));
    if (act) spA[l] = pju;
    if (l >= NPW && l < BUFW) { spA[l] = 0u; spB[l] = 0u; }   // zero pads once
    __syncthreads();

    unsigned efu = s_ef[1 * NPW + lc];
    int      m   = s_mask[1];

    // t = 1..508 in groups of 4 (rescale on 4th), tail 509..511
    for (int t = 1; t + 3 < SEQ; t += 4) {
        fwd_step<false>(t,     l, act, spA, spB, et2, efu, m, pju, offset, s_ef, s_mask, lc);
        fwd_step<false>(t + 1, l, act, spB, spA, et2, efu, m, pju, offset, s_ef, s_mask, lc);
        fwd_step<false>(t + 2, l, act, spA, spB, et2, efu, m, pju, offset, s_ef, s_mask, lc);
        fwd_step<true >(t + 3, l, act, spB, spA, et2, efu, m, pju, offset, s_ef, s_mask, lc);
    }
    fwd_step<false>(SEQ - 3, l, act, spA, spB, et2, efu, m, pju, offset, s_ef, s_mask, lc);
    fwd_step<false>(SEQ - 2, l, act, spB, spA, et2, efu, m, pju, offset, s_ef, s_mask, lc);
    fwd_step<false>(SEQ - 1, l, act, spA, spB, et2, efu, m, pju, offset, s_ef, s_mask, lc);
    // final partition lives in spB

    // terminal: s = P x exp(trans); column STOP=49 = high half of lane 24
    unsigned wf[BUFW];
#pragma unroll
    for (int q = 0; q < 7; q++) {
        float4 v = ((const float4*)spB)[q];
        wf[4 * q + 0] = __float_as_uint(v.x);
        wf[4 * q + 1] = __float_as_uint(v.y);
        wf[4 * q + 2] = __float_as_uint(v.z);
        wf[4 * q + 3] = __float_as_uint(v.w);
    }
    __nv_bfloat162 s2 = gemv25(wf, et2);
    unsigned su = __shfl_sync(0xffffffffu, b2u(s2), 24);
    float fwd = __logf(__high2float(u2b(su))) + offset;

    // ---- gold score (same warp) ----
    float acc = 0.f;
    int   len = 0;
#pragma unroll 4
    for (int t = l; t < SEQ; t += NTHR) {
        int tag  = tb[t];
        int prev = (t == 0) ? TSTART : tb[t - 1];
        int mm   = s_mask[t];
        if (mm) acc += fb[t * NTAG + tag] + trans[prev * NTAG + tag];
        len += mm;
    }
    acc = warpSumF(acc);
    len = warpSumI(len);

    if (l == 0) {
        int   endid = tb[len - 1];
        float gold  = acc + trans[endid * NTAG + TSTOP];
        g_partial[b] = fwd - gold;
        __threadfence();
        unsigned tk = atomicAdd(&g_ticket, 1u);
        s_red = (tk == BATCH - 1) ? 1.f : 0.f;
    }
    __syncthreads();

    // last CTA out: reduce the 64 batch values, reset ticket (graph-replay safe)
    if (s_red != 0.f) {
        float v = ((volatile float*)g_partial)[l] + ((volatile float*)g_partial)[l + 32];
        v = warpSumF(v);
        if (l == 0) {
            out[0] = v;
            g_ticket = 0;
        }
    }
}

extern "C" void kernel_launch(void* const* d_in, const int* in_sizes, int n_in,
                              void* d_out, int out_size)
{
    const float* feats = (const float*)d_in[0];
    const int*   mask  = (const int*)d_in[1];
    const int*   tags  = (const int*)d_in[2];
    const float* trans = (const float*)d_in[3];
    float* out = (float*)d_out;

    cudaFuncSetAttribute(crf_kernel,
                         cudaFuncAttributeMaxDynamicSharedMemorySize, SMEM_BYTES);
    crf_kernel<<<BATCH, NTHR, SMEM_BYTES>>>(feats, mask, tags, trans, out);
}

// round 10
// speedup vs baseline: 1.5150x; 1.5150x over previous
#include <cuda_runtime.h>
#include <cuda_bf16.h>
#include <math_constants.h>

// CRF neg-log-likelihood, GB300 sm_103a.
// 64 CTAs x 64 threads (2 warps). R3 skeleton: linear-space forward recursion,
// bf16 partition smem ping-pong, 25-pair HFMA2 GEMV, fp32 epilogue, rescale by
// p_prev[0] every 4 steps. DELTA vs R3: exp(feats) precomputed into dynamic
// smem (fp32) by a prologue -> loop has NO LDG, NO MUFU, NO register pipeline.

namespace {
constexpr int NTAG   = 50;
constexpr int TSTART = NTAG - 2;   // 48
constexpr int TSTOP  = NTAG - 1;   // 49
constexpr int BATCH  = 64;
constexpr int SEQ    = 512;
constexpr int NTHR   = 64;
constexpr int NPAIR  = 28;         // bf162 pairs (56 slots: 50 + 6 zero pad)
constexpr int SMEM_EF_WORDS = SEQ * NTAG;       // fp32 exp(feats), 102400 B
constexpr int SMEM_BYTES    = SMEM_EF_WORDS * 4;
}

__device__ float    g_partial[BATCH];
__device__ unsigned g_ticket = 0;

__device__ __forceinline__ float warpSumF(float v) {
#pragma unroll
    for (int o = 16; o > 0; o >>= 1) v += __shfl_xor_sync(0xffffffffu, v, o);
    return v;
}
__device__ __forceinline__ int warpSumI(int v) {
#pragma unroll
    for (int o = 16; o > 0; o >>= 1) v += __shfl_xor_sync(0xffffffffu, v, o);
    return v;
}
__device__ __forceinline__ __nv_bfloat162 asbf2(float f) {
    return *reinterpret_cast<__nv_bfloat162*>(&f);
}

// One recursion step (R3 form). ef = exp(feat[t][j]) prefetched from smem.
template <bool RESCALE>
__device__ __forceinline__ void fwd_step(
    int t, int j, int jf, bool act,
    const __nv_bfloat162* __restrict__ src,
    __nv_bfloat162*       __restrict__ dst,
    const __nv_bfloat162 (&et2)[NPAIR],
    float& ef, float& pj, float& offset,
    const float* __restrict__ s_ef,
    const int*   __restrict__ s_mask)
{
    const int m = s_mask[t];

    // issue all partition loads up front (broadcast, conflict-free)
    const float4* sp4 = (const float4*)src;
    float4 v0 = sp4[0];
    float4 v1 = sp4[1];
    float4 v2 = sp4[2];
    float4 v3 = sp4[3];
    float4 v4 = sp4[4];
    float4 v5 = sp4[5];
    float4 v6 = sp4[6];

    // rescale reciprocal off the critical path (depends only on v0.x)
    float p0f = __uint_as_float(__float_as_uint(v0.x) << 16);  // low bf16 of pair 0
    float rp0 = 1.f;
    if (RESCALE) rp0 = __frcp_rn(p0f);

    __nv_bfloat162 z  = __floats2bfloat162_rn(0.f, 0.f);
    __nv_bfloat162 a0 = z, a1 = z, a2 = z, a3 = z;

    a0 = __hfma2(asbf2(v0.x), et2[0],  a0);
    a1 = __hfma2(asbf2(v0.y), et2[1],  a1);
    a2 = __hfma2(asbf2(v0.z), et2[2],  a2);
    a3 = __hfma2(asbf2(v0.w), et2[3],  a3);
    a0 = __hfma2(asbf2(v1.x), et2[4],  a0);
    a1 = __hfma2(asbf2(v1.y), et2[5],  a1);
    a2 = __hfma2(asbf2(v1.z), et2[6],  a2);
    a3 = __hfma2(asbf2(v1.w), et2[7],  a3);
    a0 = __hfma2(asbf2(v2.x), et2[8],  a0);
    a1 = __hfma2(asbf2(v2.y), et2[9],  a1);
    a2 = __hfma2(asbf2(v2.z), et2[10], a2);
    a3 = __hfma2(asbf2(v2.w), et2[11], a3);
    a0 = __hfma2(asbf2(v3.x), et2[12], a0);
    a1 = __hfma2(asbf2(v3.y), et2[13], a1);
    a2 = __hfma2(asbf2(v3.z), et2[14], a2);
    a3 = __hfma2(asbf2(v3.w), et2[15], a3);
    a0 = __hfma2(asbf2(v4.x), et2[16], a0);
    a1 = __hfma2(asbf2(v4.y), et2[17], a1);
    a2 = __hfma2(asbf2(v4.z), et2[18], a2);
    a3 = __hfma2(asbf2(v4.w), et2[19], a3);
    a0 = __hfma2(asbf2(v5.x), et2[20], a0);
    a1 = __hfma2(asbf2(v5.y), et2[21], a1);
    a2 = __hfma2(asbf2(v5.z), et2[22], a2);
    a3 = __hfma2(asbf2(v5.w), et2[23], a3);
    a0 = __hfma2(asbf2(v6.x), et2[24], a0);
    a1 = __hfma2(asbf2(v6.y), et2[25], a1);
    a2 = __hfma2(asbf2(v6.z), et2[26], a2);
    a3 = __hfma2(asbf2(v6.w), et2[27], a3);

    a0 = __hadd2(a0, a1);
    a2 = __hadd2(a2, a3);
    a0 = __hadd2(a0, a2);
    float2 sf = __bfloat1622float2(a0);
    float  q  = (sf.x + sf.y) * ef;

    q = m ? q : pj;                 // masked step: carry previous partition

    if (RESCALE) {
        q *= rp0;
        offset += __logf(p0f);      // off critical path
    }

    pj = q;
    if (act) ((__nv_bfloat16*)dst)[j] = __float2bfloat16(q);

    // prefetch next step's exp(feat) from smem (cheap LDS, off-path)
    ef = s_ef[(t + 1) * NTAG + jf];

    __syncthreads();                // BAR.SYNC 0, nw=2; drains STS
}

__global__ void __launch_bounds__(NTHR, 1)
crf_kernel(const float* __restrict__ feats,
           const int*   __restrict__ mask,
           const int*   __restrict__ tags,
           const float* __restrict__ trans,
           float*       __restrict__ out)
{
    const int b    = blockIdx.x;
    const int j    = threadIdx.x;
    const int jf   = min(j, NTAG - 1);
    const int lane = j & 31;
    const int wid  = j >> 5;
    const bool act = (j < NTAG);

    extern __shared__ float s_ef[];          // [SEQ][NTAG] fp32 exp(feats)

    __shared__ __align__(16) __nv_bfloat162 spA[NPAIR];
    __shared__ __align__(16) __nv_bfloat162 spB[NPAIR];
    __shared__ float s_fwd;
    __shared__ float s_acc[2];
    __shared__ int   s_len[2];
    __shared__ int   s_mask[SEQ + 1];        // +1: ef prefetch guard not needed, mask is
    __shared__ bool  s_last;
    __shared__ float s_red2[2];

    const float* fb = feats + (long long)b * SEQ * NTAG;
    const int*   mb = mask  + b * SEQ;
    const int*   tb = tags  + b * SEQ;

    // ---- prologue: mask + exp(feats) whole row into smem ----
    for (int t = j; t < SEQ; t += NTHR) s_mask[t] = mb[t];
    if (j == 0) s_mask[SEQ] = 0;

    {
        const float4* f4 = (const float4*)fb;    // SEQ*NTAG/4 = 6400 float4
#pragma unroll 4
        for (int idx = j; idx < SEQ * NTAG / 4; idx += NTHR) {
            float4 v = f4[idx];
            float4 e;
            e.x = __expf(v.x);
            e.y = __expf(v.y);
            e.z = __expf(v.z);
            e.w = __expf(v.w);
            ((float4*)s_ef)[idx] = e;
        }
    }

    // exp(transitions) column j as bf162 pairs (thread j owns next-tag j)
    __nv_bfloat162 et2[NPAIR];
#pragma unroll
    for (int k = 0; k < NPAIR; k++) et2[k] = __floats2bfloat162_rn(0.f, 0.f);
    if (act) {
#pragma unroll
        for (int k = 0; k < 25; k++) {
            float e0 = __expf(trans[(2 * k)     * NTAG + j]);
            float e1 = __expf(trans[(2 * k + 1) * NTAG + j]);
            et2[k] = __floats2bfloat162_rn(e0, e1);
        }
    }

    // t = 0: normalize by partition0[tag 0] (per-thread computable)
    const float off0   = fb[0] + trans[TSTART * NTAG + 0];
    float       offset = off0;
    float pj = 0.f;
    if (act) pj = __expf(fb[j] + trans[TSTART * NTAG + j] - off0);
    if (j < 2 * NPAIR) {
        ((__nv_bfloat16*)spA)[j] = __float2bfloat16(act ? pj : 0.f);
        ((__nv_bfloat16*)spB)[j] = __float2bfloat16(0.f);   // zero pads once
    }
    __syncthreads();                       // covers prologue writes

    float ef = s_ef[1 * NTAG + jf];        // exp(feat[1][j])

    // groups of 4 steps: t = 1..508, rescale on the 4th of each group
    for (int t = 1; t + 3 < SEQ; t += 4) {
        fwd_step<false>(t,     j, jf, act, spA, spB, et2, ef, pj, offset, s_ef, s_mask);
        fwd_step<false>(t + 1, j, jf, act, spB, spA, et2, ef, pj, offset, s_ef, s_mask);
        fwd_step<false>(t + 2, j, jf, act, spA, spB, et2, ef, pj, offset, s_ef, s_mask);
        fwd_step<true >(t + 3, j, jf, act, spB, spA, et2, ef, pj, offset, s_ef, s_mask);
    }
    // tail: t = 509, 510, 511 (ef prefetch at t=511 reads s_ef[512*50] -> clamp)
    fwd_step<false>(SEQ - 3, j, jf, act, spA, spB, et2, ef, pj, offset, s_ef, s_mask);
    fwd_step<false>(SEQ - 2, j, jf, act, spB, spA, et2, ef, pj, offset, s_ef, s_mask);
    {
        // final step inline to avoid out-of-bounds ef prefetch
        const int m = s_mask[SEQ - 1];
        const float4* sp4 = (const float4*)spA;
        float4 v0 = sp4[0], v1 = sp4[1], v2 = sp4[2], v3 = sp4[3];
        float4 v4 = sp4[4], v5 = sp4[5], v6 = sp4[6];
        __nv_bfloat162 z  = __floats2bfloat162_rn(0.f, 0.f);
        __nv_bfloat162 a0 = z, a1 = z, a2 = z, a3 = z;
        a0 = __hfma2(asbf2(v0.x), et2[0],  a0);
        a1 = __hfma2(asbf2(v0.y), et2[1],  a1);
        a2 = __hfma2(asbf2(v0.z), et2[2],  a2);
        a3 = __hfma2(asbf2(v0.w), et2[3],  a3);
        a0 = __hfma2(asbf2(v1.x), et2[4],  a0);
        a1 = __hfma2(asbf2(v1.y), et2[5],  a1);
        a2 = __hfma2(asbf2(v1.z), et2[6],  a2);
        a3 = __hfma2(asbf2(v1.w), et2[7],  a3);
        a0 = __hfma2(asbf2(v2.x), et2[8],  a0);
        a1 = __hfma2(asbf2(v2.y), et2[9],  a1);
        a2 = __hfma2(asbf2(v2.z), et2[10], a2);
        a3 = __hfma2(asbf2(v2.w), et2[11], a3);
        a0 = __hfma2(asbf2(v3.x), et2[12], a0);
        a1 = __hfma2(asbf2(v3.y), et2[13], a1);
        a2 = __hfma2(asbf2(v3.z), et2[14], a2);
        a3 = __hfma2(asbf2(v3.w), et2[15], a3);
        a0 = __hfma2(asbf2(v4.x), et2[16], a0);
        a1 = __hfma2(asbf2(v4.y), et2[17], a1);
        a2 = __hfma2(asbf2(v4.z), et2[18], a2);
        a3 = __hfma2(asbf2(v4.w), et2[19], a3);
        a0 = __hfma2(asbf2(v5.x), et2[20], a0);
        a1 = __hfma2(asbf2(v5.y), et2[21], a1);
        a2 = __hfma2(asbf2(v5.z), et2[22], a2);
        a3 = __hfma2(asbf2(v5.w), et2[23], a3);
        a0 = __hfma2(asbf2(v6.x), et2[24], a0);
        a1 = __hfma2(asbf2(v6.y), et2[25], a1);
        a2 = __hfma2(asbf2(v6.z), et2[26], a2);
        a3 = __hfma2(asbf2(v6.w), et2[27], a3);
        a0 = __hadd2(a0, a1);
        a2 = __hadd2(a2, a3);
        a0 = __hadd2(a0, a2);
        float2 sf = __bfloat1622float2(a0);
        float  q  = (sf.x + sf.y) * ef;
        q = m ? q : pj;
        pj = q;
        if (act) ((__nv_bfloat16*)spB)[j] = __float2bfloat16(q);
        __syncthreads();
    }
    // final partition lives in spB

    // terminal: forward = log( sum_i p[i] * exp(trans[i,STOP]) ) + offset
    if (j == TSTOP) {
        const float4* sp4 = (const float4*)spB;
        __nv_bfloat162 z  = __floats2bfloat162_rn(0.f, 0.f);
        __nv_bfloat162 a0 = z, a1 = z, a2 = z, a3 = z;
#pragma unroll
        for (int k = 0; k < 7; k++) {
            float4 v = sp4[k];
            a0 = __hfma2(asbf2(v.x), et2[4 * k + 0], a0);
            a1 = __hfma2(asbf2(v.y), et2[4 * k + 1], a1);
            a2 = __hfma2(asbf2(v.z), et2[4 * k + 2], a2);
            a3 = __hfma2(asbf2(v.w), et2[4 * k + 3], a3);
        }
        a0 = __hadd2(a0, a1);
        a2 = __hadd2(a2, a3);
        a0 = __hadd2(a0, a2);
        float2 sf = __bfloat1622float2(a0);
        s_fwd = __logf(sf.x + sf.y) + offset;
    }

    // ---- gold score (all 64 threads, epilogue) ----
    float acc = 0.f;
    int   len = 0;
#pragma unroll
    for (int t = j; t < SEQ; t += NTHR) {
        int tag  = tb[t];
        int prev = (t == 0) ? TSTART : tb[t - 1];
        int mm   = s_mask[t];
        if (mm) acc += fb[t * NTAG + tag] + trans[prev * NTAG + tag];
        len += mm;
    }
    acc = warpSumF(acc);
    len = warpSumI(len);
    if (lane == 0) { s_acc[wid] = acc; s_len[wid] = len; }
    __syncthreads();

    if (j == 0) {
        int   L     = s_len[0] + s_len[1];
        int   endid = tb[L - 1];
        float gold  = s_acc[0] + s_acc[1] + trans[endid * NTAG + TSTOP];
        g_partial[b] = s_fwd - gold;
        __threadfence();
        unsigned tk = atomicAdd(&g_ticket, 1u);
        s_last = (tk == BATCH - 1);
    }
    __syncthreads();

    // last CTA out: reduce all 64 batch values, reset ticket (graph-replay safe)
    if (s_last) {
        float v = ((volatile float*)g_partial)[j];
        v = warpSumF(v);
        if (lane == 0) s_red2[wid] = v;
        __syncthreads();
        if (j == 0) {
            out[0] = s_red2[0] + s_red2[1];
            g_ticket = 0;
        }
    }
}

extern "C" void kernel_launch(void* const* d_in, const int* in_sizes, int n_in,
                              void* d_out, int out_size)
{
    const float* feats = (const float*)d_in[0];
    const int*   mask  = (const int*)d_in[1];
    const int*   tags  = (const int*)d_in[2];
    const float* trans = (const float*)d_in[3];
    float* out = (float*)d_out;

    cudaFuncSetAttribute(crf_kernel,
                         cudaFuncAttributeMaxDynamicSharedMemorySize, SMEM_BYTES);
    crf_kernel<<<BATCH, NTHR, SMEM_BYTES>>>(feats, mask, tags, trans, out);
}